// round 13
// baseline (speedup 1.0000x reference)
#include <cuda_runtime.h>
#include <cuda_fp16.h>
#include <cstdint>

#define TOKENS 8192
#define DMODEL 1024
#define VOCAB  32000
#define MTILE  128
#define NTILE  256
#define KC     64                  // fp16 per K-chunk (128 B rows)
#define NCHUNKS (DMODEL / KC)      // 16
#define NST    2
#define MTILES_M (TOKENS / MTILE)  // 64
#define NTILES_N (VOCAB / NTILE)   // 125
#define NTILES   (MTILES_M * NTILES_N)  // 8000
#define GRID_MAIN 296              // 2 CTAs / SM
#define XBLKS 1024
#define WBLKS 4096

// -------- scratch (device globals: allocation-free rule) --------
__device__ __half g_xb[TOKENS * DMODEL];        // 16 MB
__device__ __half g_wb[(size_t)VOCAB * DMODEL]; // 64 MB
__device__ float g_tscore[TOKENS];
__device__ float g_ph[4 * (size_t)NTILES_N * TOKENS];  // 16 MB (per-N-quarter partials)
__device__ float g_bsum[32];

// -------- helpers --------
__device__ __forceinline__ uint32_t smem_u32(const void* p) {
    uint32_t a;
    asm("{ .reg .u64 t; cvta.to.shared.u64 t, %1; cvt.u32.u64 %0, t; }"
        : "=r"(a) : "l"(p));
    return a;
}
__device__ __forceinline__ uint32_t swz(uint32_t off) {   // SW128
    return off ^ ((off >> 3) & 0x70);
}
__device__ __forceinline__ void wait_parity(uint32_t mbar, uint32_t parity) {
    asm volatile(
        "{\n\t"
        ".reg .pred P1;\n\t"
        "WAIT_LOOP_%=:\n\t"
        "mbarrier.try_wait.parity.acquire.cta.shared::cta.b64 P1, [%0], %1, 0x989680;\n\t"
        "@P1 bra.uni WAIT_DONE_%=;\n\t"
        "bra.uni WAIT_LOOP_%=;\n\t"
        "WAIT_DONE_%=:\n\t"
        "}"
        :: "r"(mbar), "r"(parity) : "memory");
}

// -------- kernel 1: fused prep (x->fp16 | w->fp16 | exact tscore) --------
__global__ void prep_kernel(const float* __restrict__ x,
                            const float* __restrict__ w,
                            const int* __restrict__ tgt) {
    int b = blockIdx.x;
    int tid = threadIdx.x;
    if (b < XBLKS) {
        int i = b * 256 + tid;
        int stride = XBLKS * 256;
        int n4 = TOKENS * DMODEL / 4;
        for (; i < n4; i += stride) {
            float4 v = ((const float4*)x)[i];
            ((__half2*)g_xb)[2 * i]     = __floats2half2_rn(v.x, v.y);
            ((__half2*)g_xb)[2 * i + 1] = __floats2half2_rn(v.z, v.w);
        }
    } else if (b < XBLKS + WBLKS) {
        size_t i = (size_t)(b - XBLKS) * 256 + tid;
        size_t stride = (size_t)WBLKS * 256;
        size_t n4 = (size_t)VOCAB * DMODEL / 4;
        for (; i < n4; i += stride) {
            float4 v = ((const float4*)w)[i];
            ((__half2*)g_wb)[2 * i]     = __floats2half2_rn(v.x, v.y);
            ((__half2*)g_wb)[2 * i + 1] = __floats2half2_rn(v.z, v.w);
        }
    } else {
        int t = b - (XBLKS + WBLKS);        // one token per block
        const float4* xr = (const float4*)(x + (size_t)t * DMODEL);
        const float4* wr = (const float4*)(w + (size_t)tgt[t] * DMODEL);
        float4 a = xr[tid], c = wr[tid];    // 256 float4 = full row
        float s = a.x * c.x + a.y * c.y + a.z * c.z + a.w * c.w;
#pragma unroll
        for (int o = 16; o; o >>= 1) s += __shfl_xor_sync(0xFFFFFFFFu, s, o);
        __shared__ float ws[8];
        if ((tid & 31) == 0) ws[tid >> 5] = s;
        __syncthreads();
        if (tid == 0) {
            float r = 0.f;
#pragma unroll
            for (int i = 0; i < 8; ++i) r += ws[i];
            g_tscore[t] = r;
        }
    }
}

// -------- kernel 2: persistent GEMM (f16 acc, 64x64 warp tile) --------
__device__ __forceinline__ void load_chunk(const __half* asrc,
                                           const __half* bsrc,
                                           uint32_t stA, int tid) {
    uint32_t stB = stA + MTILE * 128;
#pragma unroll
    for (int j = 0; j < 4; ++j) {            // A: 128 rows x 8 segs of 16B
        int l = tid + 256 * j;
        int row = l >> 3, seg = l & 7;
        uint32_t dst = stA + swz((uint32_t)(row * 128 + seg * 16));
        const char* src = (const char*)asrc + (size_t)row * (DMODEL * 2) + seg * 16;
        asm volatile("cp.async.cg.shared.global [%0], [%1], 16;" :: "r"(dst), "l"(src));
    }
#pragma unroll
    for (int j = 0; j < 8; ++j) {            // B: 256 rows x 8 segs of 16B
        int l = tid + 256 * j;
        int row = l >> 3, seg = l & 7;
        uint32_t dst = stB + swz((uint32_t)(row * 128 + seg * 16));
        const char* src = (const char*)bsrc + (size_t)row * (DMODEL * 2) + seg * 16;
        asm volatile("cp.async.cg.shared.global [%0], [%1], 16;" :: "r"(dst), "l"(src));
    }
}

__global__ void __launch_bounds__(256, 2) mevo_main_kernel() {
    extern __shared__ char sm[];
    const uint32_t STAGE = (MTILE + NTILE) * 128;   // 49152
    uint32_t raw  = smem_u32(sm);
    uint32_t base = (raw + 1023u) & ~1023u;
    uint32_t mb   = base + NST * STAGE;   // mbarriers: full[0..1], empty[0..1]

    int tid = threadIdx.x;
    int wid = tid >> 5, lid = tid & 31;
    int wm = wid & 1, wn = wid >> 1;        // 2(m) x 4(n) warp grid
    int bid = blockIdx.x;

    int ntiles_mine = (NTILES - 1 - bid) / GRID_MAIN + 1;
    int qtot = ntiles_mine * NCHUNKS;

    if (tid == 0) {
#pragma unroll
        for (int s = 0; s < NST; ++s) {
            asm volatile("mbarrier.init.shared.b64 [%0], 256;"
                         :: "r"(mb + 8u * s) : "memory");            // full[s]
            asm volatile("mbarrier.init.shared.b64 [%0], 256;"
                         :: "r"(mb + 8u * (NST + s)) : "memory");    // empty[s]
        }
    }
    __syncthreads();   // only CTA-wide sync in the kernel

    const int rbase  = wm * 64;
    const int nbase  = wn * 64;
    const int arow_l = lid & 15;
    const uint32_t akb_l = (uint32_t)((lid >> 4) << 4);
    const int brow_l = lid & 7;
    const int bpair_l = (lid >> 4) & 1;
    const uint32_t bkb_l = (uint32_t)(((lid >> 3) & 1) << 4);

    // f16 accumulators: 4 m-frags x 8 n-frags x 2 regs = 64 regs
    uint32_t acc[4][8][2];
#pragma unroll
    for (int i = 0; i < 4; ++i)
#pragma unroll
        for (int j = 0; j < 8; ++j) { acc[i][j][0] = 0u; acc[i][j][1] = 0u; }

    // issue loads for flat chunk index q into stage q%2, arrive (noinc) on full
    auto issue = [&](int q) {
        int T = bid + (q >> 4) * GRID_MAIN;
        int c = q & 15;
        const __half* asrc = g_xb + (size_t)(T % MTILES_M) * MTILE * DMODEL
                                  + (size_t)c * KC;
        const __half* bsrc = g_wb + (size_t)(T / MTILES_M) * NTILE * DMODEL
                                  + (size_t)c * KC;
        uint32_t st = base + (uint32_t)(q % NST) * STAGE;
        load_chunk(asrc, bsrc, st, tid);
        asm volatile("cp.async.mbarrier.arrive.noinc.shared.b64 [%0];"
                     :: "r"(mb + 8u * (uint32_t)(q % NST)) : "memory");
    };

    // prologue: chunk 0
    if (qtot > 0) issue(0);

    for (int q = 0; q < qtot; ++q) {
        // producer: chunk q+1 into stage (q+1)%2 (consumed at q-1)
        int qp = q + NST - 1;
        if (qp < qtot && qp > 0) {
            uint32_t sp = (uint32_t)(qp % NST);
            uint32_t kp = (uint32_t)(qp / NST);
            wait_parity(mb + 8u * (NST + sp), (kp & 1u) ^ 1u);
            issue(qp);
        }

        // consumer: chunk q
        uint32_t s0 = (uint32_t)(q % NST);
        uint32_t k0 = (uint32_t)(q / NST);
        wait_parity(mb + 8u * s0, k0 & 1u);

        uint32_t Ab = base + s0 * STAGE;
        uint32_t Bb = Ab + MTILE * 128;

#pragma unroll
        for (int s = 0; s < 4; ++s) {
            uint32_t kb = (uint32_t)(s * 32);
            uint32_t a[4][4];
#pragma unroll
            for (int mf = 0; mf < 4; ++mf) {
                uint32_t addr = Ab + swz((uint32_t)((rbase + mf * 16 + arow_l) * 128)
                                         + kb + akb_l);
                asm volatile("ldmatrix.sync.aligned.m8n8.x4.shared.b16 "
                             "{%0,%1,%2,%3}, [%4];"
                             : "=r"(a[mf][0]), "=r"(a[mf][1]),
                               "=r"(a[mf][2]), "=r"(a[mf][3])
                             : "r"(addr));
            }
            uint32_t b[8][2];
#pragma unroll
            for (int np = 0; np < 4; ++np) {
                uint32_t addr = Bb + swz(
                    (uint32_t)((nbase + (np * 2 + bpair_l) * 8 + brow_l) * 128)
                    + kb + bkb_l);
                asm volatile("ldmatrix.sync.aligned.m8n8.x4.shared.b16 "
                             "{%0,%1,%2,%3}, [%4];"
                             : "=r"(b[np * 2][0]),     "=r"(b[np * 2][1]),
                               "=r"(b[np * 2 + 1][0]), "=r"(b[np * 2 + 1][1])
                             : "r"(addr));
            }
#pragma unroll
            for (int mf = 0; mf < 4; ++mf)
#pragma unroll
                for (int nf = 0; nf < 8; ++nf)
                    asm volatile(
                        "mma.sync.aligned.m16n8k16.row.col.f16.f16.f16.f16 "
                        "{%0,%1}, {%2,%3,%4,%5}, {%6,%7}, {%0,%1};"
                        : "+r"(acc[mf][nf][0]), "+r"(acc[mf][nf][1])
                        : "r"(a[mf][0]), "r"(a[mf][1]), "r"(a[mf][2]), "r"(a[mf][3]),
                          "r"(b[nf][0]), "r"(b[nf][1]));
        }

        // done reading stage s0
        asm volatile("mbarrier.arrive.shared.b64 _, [%0];"
                     :: "r"(mb + 8u * (NST + s0)) : "memory");

        if ((q & 15) == 15) {
            // ---- tile epilogue: per-warp exp-sum, direct global write ----
            int T = bid + (q >> 4) * GRID_MAIN;
            int m0 = (T % MTILES_M) * MTILE;
            int ny = T / MTILES_M;

            float rs[4][2];
#pragma unroll
            for (int mf = 0; mf < 4; ++mf) { rs[mf][0] = 0.f; rs[mf][1] = 0.f; }
#pragma unroll
            for (int mf = 0; mf < 4; ++mf)
#pragma unroll
                for (int nf = 0; nf < 8; ++nf) {
                    float2 v0 = __half22float2(*(const __half2*)&acc[mf][nf][0]);
                    float2 v1 = __half22float2(*(const __half2*)&acc[mf][nf][1]);
                    rs[mf][0] += __expf(v0.x) + __expf(v0.y);
                    rs[mf][1] += __expf(v1.x) + __expf(v1.y);
                }
#pragma unroll
            for (int mf = 0; mf < 4; ++mf)
#pragma unroll
                for (int h = 0; h < 2; ++h) {
                    rs[mf][h] += __shfl_xor_sync(0xFFFFFFFFu, rs[mf][h], 1);
                    rs[mf][h] += __shfl_xor_sync(0xFFFFFFFFu, rs[mf][h], 2);
                }
            if ((lid & 3) == 0) {
                int g = lid >> 2;
                float* dst = g_ph + ((size_t)wn * NTILES_N + ny) * TOKENS + m0;
#pragma unroll
                for (int mf = 0; mf < 4; ++mf) {
                    dst[rbase + mf * 16 + g]     = rs[mf][0];
                    dst[rbase + mf * 16 + g + 8] = rs[mf][1];
                }
            }
#pragma unroll
            for (int i = 0; i < 4; ++i)
#pragma unroll
                for (int j = 0; j < 8; ++j) { acc[i][j][0] = 0u; acc[i][j][1] = 0u; }
        }
    }
}

// -------- kernel 3: finalize (two stage) --------
__global__ void finalize_kernel() {
    __shared__ float red[256];
    int r0 = blockIdx.x * (TOKENS / 32);
    float acc = 0.f;
    for (int r = r0 + threadIdx.x; r < r0 + TOKENS / 32; r += 256) {
        float s = 0.f;
        for (int p = 0; p < 4 * NTILES_N; ++p) s += g_ph[(size_t)p * TOKENS + r];
        acc += logf(s) - g_tscore[r];
    }
    red[threadIdx.x] = acc;
    __syncthreads();
    for (int o = 128; o; o >>= 1) {
        if (threadIdx.x < o) red[threadIdx.x] += red[threadIdx.x + o];
        __syncthreads();
    }
    if (threadIdx.x == 0) g_bsum[blockIdx.x] = red[0];
}
__global__ void finalize2_kernel(float* __restrict__ out) {
    if (threadIdx.x == 0) {
        float s = 0.f;
        for (int i = 0; i < 32; ++i) s += g_bsum[i];
        out[0] = s;
    }
}

// -------- launch --------
extern "C" void kernel_launch(void* const* d_in, const int* in_sizes, int n_in,
                              void* d_out, int out_size) {
    (void)in_sizes; (void)n_in; (void)out_size;
    const float* x = (const float*)d_in[0];
    const float* w = (const float*)d_in[1];
    const int*   t = (const int*)d_in[2];
    float* out = (float*)d_out;

    const uint32_t STAGE = (MTILE + NTILE) * 128;   // 48 KB
    const int SMEM_BYTES = 1024 + NST * STAGE + 256;   // ~99.5 KB

    cudaFuncSetAttribute(mevo_main_kernel,
                         cudaFuncAttributeMaxDynamicSharedMemorySize, SMEM_BYTES);

    prep_kernel<<<XBLKS + WBLKS + TOKENS, 256>>>(x, w, t);
    mevo_main_kernel<<<GRID_MAIN, 256, SMEM_BYTES>>>();
    finalize_kernel<<<32, 256>>>();
    finalize2_kernel<<<1, 32>>>(out);
}

// round 14
// speedup vs baseline: 1.0790x; 1.0790x over previous
#include <cuda_runtime.h>
#include <cuda_fp16.h>
#include <cstdint>

#define TOKENS 8192
#define DMODEL 1024
#define VOCAB  32000
#define MTILE  128
#define NTILE  128
#define KC     64                  // fp16 per K-chunk (128 B rows)
#define NCHUNKS (DMODEL / KC)      // 16
#define NST    3
#define NTHREADS 128
#define MTILES_M (TOKENS / MTILE)  // 64
#define NTILES_N (VOCAB / NTILE)   // 250
#define NTILES   (MTILES_M * NTILES_N)  // 16000
#define GRID_MAIN 296              // 2 CTAs / SM
#define XBLKS 1024
#define WBLKS 4096

// -------- scratch (device globals: allocation-free rule) --------
__device__ __half g_xb[TOKENS * DMODEL];        // 16 MB
__device__ __half g_wb[(size_t)VOCAB * DMODEL]; // 64 MB
__device__ float g_tscore[TOKENS];
__device__ float g_ph[2 * (size_t)NTILES_N * TOKENS];  // 16 MB (per-N-half partials)
__device__ float g_bsum[32];

// -------- helpers --------
__device__ __forceinline__ uint32_t smem_u32(const void* p) {
    uint32_t a;
    asm("{ .reg .u64 t; cvta.to.shared.u64 t, %1; cvt.u32.u64 %0, t; }"
        : "=r"(a) : "l"(p));
    return a;
}
__device__ __forceinline__ uint32_t swz(uint32_t off) {   // SW128
    return off ^ ((off >> 3) & 0x70);
}
__device__ __forceinline__ void wait_parity(uint32_t mbar, uint32_t parity) {
    asm volatile(
        "{\n\t"
        ".reg .pred P1;\n\t"
        "WAIT_LOOP_%=:\n\t"
        "mbarrier.try_wait.parity.acquire.cta.shared::cta.b64 P1, [%0], %1, 0x989680;\n\t"
        "@P1 bra.uni WAIT_DONE_%=;\n\t"
        "bra.uni WAIT_LOOP_%=;\n\t"
        "WAIT_DONE_%=:\n\t"
        "}"
        :: "r"(mbar), "r"(parity) : "memory");
}

// -------- kernel 1: fused prep (x->fp16 | w->fp16 | exact tscore) --------
__global__ void prep_kernel(const float* __restrict__ x,
                            const float* __restrict__ w,
                            const int* __restrict__ tgt) {
    int b = blockIdx.x;
    int tid = threadIdx.x;
    if (b < XBLKS) {
        int i = b * 256 + tid;
        int stride = XBLKS * 256;
        int n4 = TOKENS * DMODEL / 4;
        for (; i < n4; i += stride) {
            float4 v = ((const float4*)x)[i];
            ((__half2*)g_xb)[2 * i]     = __floats2half2_rn(v.x, v.y);
            ((__half2*)g_xb)[2 * i + 1] = __floats2half2_rn(v.z, v.w);
        }
    } else if (b < XBLKS + WBLKS) {
        size_t i = (size_t)(b - XBLKS) * 256 + tid;
        size_t stride = (size_t)WBLKS * 256;
        size_t n4 = (size_t)VOCAB * DMODEL / 4;
        for (; i < n4; i += stride) {
            float4 v = ((const float4*)w)[i];
            ((__half2*)g_wb)[2 * i]     = __floats2half2_rn(v.x, v.y);
            ((__half2*)g_wb)[2 * i + 1] = __floats2half2_rn(v.z, v.w);
        }
    } else {
        int t = b - (XBLKS + WBLKS);        // one token per block
        const float4* xr = (const float4*)(x + (size_t)t * DMODEL);
        const float4* wr = (const float4*)(w + (size_t)tgt[t] * DMODEL);
        float4 a = xr[tid], c = wr[tid];    // 256 float4 = full row
        float s = a.x * c.x + a.y * c.y + a.z * c.z + a.w * c.w;
#pragma unroll
        for (int o = 16; o; o >>= 1) s += __shfl_xor_sync(0xFFFFFFFFu, s, o);
        __shared__ float ws[8];
        if ((tid & 31) == 0) ws[tid >> 5] = s;
        __syncthreads();
        if (tid == 0) {
            float r = 0.f;
#pragma unroll
            for (int i = 0; i < 8; ++i) r += ws[i];
            g_tscore[t] = r;
        }
    }
}

// -------- kernel 2: persistent GEMM (f16 acc, 64x64 warp tile, 4 warps) ----
__device__ __forceinline__ void load_chunk(const __half* asrc,
                                           const __half* bsrc,
                                           uint32_t stA, int tid) {
    uint32_t stB = stA + MTILE * 128;
#pragma unroll
    for (int j = 0; j < 8; ++j) {            // A: 128 rows x 8 segs of 16B
        int l = tid + NTHREADS * j;
        int row = l >> 3, seg = l & 7;
        uint32_t dst = stA + swz((uint32_t)(row * 128 + seg * 16));
        const char* src = (const char*)asrc + (size_t)row * (DMODEL * 2) + seg * 16;
        asm volatile("cp.async.cg.shared.global [%0], [%1], 16;" :: "r"(dst), "l"(src));
    }
#pragma unroll
    for (int j = 0; j < 8; ++j) {            // B: 128 rows x 8 segs of 16B
        int l = tid + NTHREADS * j;
        int row = l >> 3, seg = l & 7;
        uint32_t dst = stB + swz((uint32_t)(row * 128 + seg * 16));
        const char* src = (const char*)bsrc + (size_t)row * (DMODEL * 2) + seg * 16;
        asm volatile("cp.async.cg.shared.global [%0], [%1], 16;" :: "r"(dst), "l"(src));
    }
}

__global__ void __launch_bounds__(NTHREADS, 2) mevo_main_kernel() {
    extern __shared__ char sm[];
    const uint32_t STAGE = (MTILE + NTILE) * 128;   // 32768
    uint32_t raw  = smem_u32(sm);
    uint32_t base = (raw + 1023u) & ~1023u;
    uint32_t mb   = base + NST * STAGE;   // mbarriers: full[0..2], empty[0..2]

    int tid = threadIdx.x;
    int wid = tid >> 5, lid = tid & 31;
    int wm = wid & 1, wn = wid >> 1;        // 2(m) x 2(n) warp grid
    int bid = blockIdx.x;

    int ntiles_mine = (NTILES - 1 - bid) / GRID_MAIN + 1;
    int qtot = ntiles_mine * NCHUNKS;

    if (tid == 0) {
#pragma unroll
        for (int s = 0; s < NST; ++s) {
            asm volatile("mbarrier.init.shared.b64 [%0], %1;"
                         :: "r"(mb + 8u * s), "r"(NTHREADS) : "memory");   // full[s]
            asm volatile("mbarrier.init.shared.b64 [%0], %1;"
                         :: "r"(mb + 8u * (NST + s)), "r"(NTHREADS) : "memory"); // empty[s]
        }
    }
    __syncthreads();   // only CTA-wide sync in the kernel

    const int rbase  = wm * 64;
    const int nbase  = wn * 64;
    const int arow_l = lid & 15;
    const uint32_t akb_l = (uint32_t)((lid >> 4) << 4);
    const int brow_l = lid & 7;
    const int bpair_l = (lid >> 4) & 1;
    const uint32_t bkb_l = (uint32_t)(((lid >> 3) & 1) << 4);

    // f16 accumulators: 4 m-frags x 8 n-frags x 2 regs = 64 regs
    uint32_t acc[4][8][2];
#pragma unroll
    for (int i = 0; i < 4; ++i)
#pragma unroll
        for (int j = 0; j < 8; ++j) { acc[i][j][0] = 0u; acc[i][j][1] = 0u; }

    // issue loads for flat chunk index q into stage q%3, arrive (noinc) on full
    auto issue = [&](int q) {
        int T = bid + (q >> 4) * GRID_MAIN;
        int c = q & 15;
        const __half* asrc = g_xb + (size_t)(T % MTILES_M) * MTILE * DMODEL
                                  + (size_t)c * KC;
        const __half* bsrc = g_wb + (size_t)(T / MTILES_M) * NTILE * DMODEL
                                  + (size_t)c * KC;
        uint32_t st = base + (uint32_t)(q % NST) * STAGE;
        load_chunk(asrc, bsrc, st, tid);
        asm volatile("cp.async.mbarrier.arrive.noinc.shared.b64 [%0];"
                     :: "r"(mb + 8u * (uint32_t)(q % NST)) : "memory");
    };

    // prologue: chunks 0,1
#pragma unroll
    for (int s = 0; s < NST - 1; ++s)
        if (s < qtot) issue(s);

    for (int q = 0; q < qtot; ++q) {
        // producer: chunk q+2 into stage (q+2)%3 (consumed at q-1)
        int qp = q + NST - 1;
        if (qp < qtot) {
            uint32_t sp = (uint32_t)(qp % NST);
            uint32_t kp = (uint32_t)(qp / NST);
            wait_parity(mb + 8u * (NST + sp), (kp & 1u) ^ 1u);
            issue(qp);
        }

        // consumer: chunk q
        uint32_t s0 = (uint32_t)(q % NST);
        uint32_t k0 = (uint32_t)(q / NST);
        wait_parity(mb + 8u * s0, k0 & 1u);

        uint32_t Ab = base + s0 * STAGE;
        uint32_t Bb = Ab + MTILE * 128;

#pragma unroll
        for (int s = 0; s < 4; ++s) {
            uint32_t kb = (uint32_t)(s * 32);
            uint32_t a[4][4];
#pragma unroll
            for (int mf = 0; mf < 4; ++mf) {
                uint32_t addr = Ab + swz((uint32_t)((rbase + mf * 16 + arow_l) * 128)
                                         + kb + akb_l);
                asm volatile("ldmatrix.sync.aligned.m8n8.x4.shared.b16 "
                             "{%0,%1,%2,%3}, [%4];"
                             : "=r"(a[mf][0]), "=r"(a[mf][1]),
                               "=r"(a[mf][2]), "=r"(a[mf][3])
                             : "r"(addr));
            }
            uint32_t b[8][2];
#pragma unroll
            for (int np = 0; np < 4; ++np) {
                uint32_t addr = Bb + swz(
                    (uint32_t)((nbase + (np * 2 + bpair_l) * 8 + brow_l) * 128)
                    + kb + bkb_l);
                asm volatile("ldmatrix.sync.aligned.m8n8.x4.shared.b16 "
                             "{%0,%1,%2,%3}, [%4];"
                             : "=r"(b[np * 2][0]),     "=r"(b[np * 2][1]),
                               "=r"(b[np * 2 + 1][0]), "=r"(b[np * 2 + 1][1])
                             : "r"(addr));
            }
#pragma unroll
            for (int mf = 0; mf < 4; ++mf)
#pragma unroll
                for (int nf = 0; nf < 8; ++nf)
                    asm volatile(
                        "mma.sync.aligned.m16n8k16.row.col.f16.f16.f16.f16 "
                        "{%0,%1}, {%2,%3,%4,%5}, {%6,%7}, {%0,%1};"
                        : "+r"(acc[mf][nf][0]), "+r"(acc[mf][nf][1])
                        : "r"(a[mf][0]), "r"(a[mf][1]), "r"(a[mf][2]), "r"(a[mf][3]),
                          "r"(b[nf][0]), "r"(b[nf][1]));
        }

        // done reading stage s0
        asm volatile("mbarrier.arrive.shared.b64 _, [%0];"
                     :: "r"(mb + 8u * (NST + s0)) : "memory");

        if ((q & 15) == 15) {
            // ---- tile epilogue: per-warp exp-sum, direct global write ----
            int T = bid + (q >> 4) * GRID_MAIN;
            int m0 = (T % MTILES_M) * MTILE;
            int ny = T / MTILES_M;

            float rs[4][2];
#pragma unroll
            for (int mf = 0; mf < 4; ++mf) { rs[mf][0] = 0.f; rs[mf][1] = 0.f; }
#pragma unroll
            for (int mf = 0; mf < 4; ++mf)
#pragma unroll
                for (int nf = 0; nf < 8; ++nf) {
                    float2 v0 = __half22float2(*(const __half2*)&acc[mf][nf][0]);
                    float2 v1 = __half22float2(*(const __half2*)&acc[mf][nf][1]);
                    rs[mf][0] += __expf(v0.x) + __expf(v0.y);
                    rs[mf][1] += __expf(v1.x) + __expf(v1.y);
                }
#pragma unroll
            for (int mf = 0; mf < 4; ++mf)
#pragma unroll
                for (int h = 0; h < 2; ++h) {
                    rs[mf][h] += __shfl_xor_sync(0xFFFFFFFFu, rs[mf][h], 1);
                    rs[mf][h] += __shfl_xor_sync(0xFFFFFFFFu, rs[mf][h], 2);
                }
            if ((lid & 3) == 0) {
                int g = lid >> 2;
                float* dst = g_ph + ((size_t)wn * NTILES_N + ny) * TOKENS + m0;
#pragma unroll
                for (int mf = 0; mf < 4; ++mf) {
                    dst[rbase + mf * 16 + g]     = rs[mf][0];
                    dst[rbase + mf * 16 + g + 8] = rs[mf][1];
                }
            }
#pragma unroll
            for (int i = 0; i < 4; ++i)
#pragma unroll
                for (int j = 0; j < 8; ++j) { acc[i][j][0] = 0u; acc[i][j][1] = 0u; }
        }
    }
}

// -------- kernel 3: finalize (two stage) --------
__global__ void finalize_kernel() {
    __shared__ float red[256];
    int r0 = blockIdx.x * (TOKENS / 32);
    float acc = 0.f;
    for (int r = r0 + threadIdx.x; r < r0 + TOKENS / 32; r += 256) {
        float s = 0.f;
        for (int p = 0; p < 2 * NTILES_N; ++p) s += g_ph[(size_t)p * TOKENS + r];
        acc += logf(s) - g_tscore[r];
    }
    red[threadIdx.x] = acc;
    __syncthreads();
    for (int o = 128; o; o >>= 1) {
        if (threadIdx.x < o) red[threadIdx.x] += red[threadIdx.x + o];
        __syncthreads();
    }
    if (threadIdx.x == 0) g_bsum[blockIdx.x] = red[0];
}
__global__ void finalize2_kernel(float* __restrict__ out) {
    if (threadIdx.x == 0) {
        float s = 0.f;
        for (int i = 0; i < 32; ++i) s += g_bsum[i];
        out[0] = s;
    }
}

// -------- launch --------
extern "C" void kernel_launch(void* const* d_in, const int* in_sizes, int n_in,
                              void* d_out, int out_size) {
    (void)in_sizes; (void)n_in; (void)out_size;
    const float* x = (const float*)d_in[0];
    const float* w = (const float*)d_in[1];
    const int*   t = (const int*)d_in[2];
    float* out = (float*)d_out;

    const uint32_t STAGE = (MTILE + NTILE) * 128;   // 32 KB
    const int SMEM_BYTES = 1024 + NST * STAGE + 256;

    cudaFuncSetAttribute(mevo_main_kernel,
                         cudaFuncAttributeMaxDynamicSharedMemorySize, SMEM_BYTES);

    prep_kernel<<<XBLKS + WBLKS + TOKENS, 256>>>(x, w, t);
    mevo_main_kernel<<<GRID_MAIN, NTHREADS, SMEM_BYTES>>>();
    finalize_kernel<<<32, 256>>>();
    finalize2_kernel<<<1, 32>>>(out);
}